// round 6
// baseline (speedup 1.0000x reference)
#include <cuda_runtime.h>
#include <math.h>

// Problem shape (fixed by the dataset)
#define BB 16
#define NN 8192
#define KK 128
#define MM (NN + KK)          // 8320
#define FG_THRESH 0.5f

// Scratch (no allocations allowed -> __device__ globals)
__device__ float g_maxov[BB * MM];
__device__ int   g_garg [BB * MM];
__device__ int   g_dest [BB * MM];

// ---------------------------------------------------------------------------
// Kernel 1: per-roi max IoU + argmax over K gt boxes.
// Compare-critical arithmetic uses _rn intrinsics to be bitwise identical to
// the reference regardless of FMA contraction / fast-math flags.
// ---------------------------------------------------------------------------
__global__ __launch_bounds__(256)
void k_iou(const float* __restrict__ rois, const float* __restrict__ gt)
{
    __shared__ float4 s_g[KK];     // gt coords
    __shared__ float  s_ga[KK];    // gt area
    __shared__ float  s_sc[KK];    // 0 if zero-area gt else 1

    const int b = blockIdx.y;
    const int t = threadIdx.x;

    for (int k = t; k < KK; k += blockDim.x) {
        const float* g = gt + ((size_t)b * KK + k) * 5;
        float gx1 = g[0], gy1 = g[1], gx2 = g[2], gy2 = g[3];
        float gw = __fadd_rn(__fsub_rn(gx2, gx1), 1.0f);
        float gh = __fadd_rn(__fsub_rn(gy2, gy1), 1.0f);
        s_g[k]  = make_float4(gx1, gy1, gx2, gy2);
        s_ga[k] = __fmul_rn(gw, gh);
        s_sc[k] = (gw == 1.0f && gh == 1.0f) ? 0.0f : 1.0f;
    }
    __syncthreads();

    const int m = blockIdx.x * blockDim.x + t;
    if (m >= MM) return;

    float x1, y1, x2, y2;
    if (m < NN) {
        const float* r = rois + ((size_t)b * NN + m) * 5;
        x1 = r[1]; y1 = r[2]; x2 = r[3]; y2 = r[4];
    } else {
        const float* g = gt + ((size_t)b * KK + (m - NN)) * 5;
        x1 = g[0]; y1 = g[1]; x2 = g[2]; y2 = g[3];
    }

    float aw    = __fadd_rn(__fsub_rn(x2, x1), 1.0f);
    float ah    = __fadd_rn(__fsub_rn(y2, y1), 1.0f);
    float areaA = __fmul_rn(aw, ah);

    float best  = -1e30f;
    int   bestk = 0;

#pragma unroll 4
    for (int k = 0; k < KK; k++) {
        float4 g  = s_g[k];
        float ix1 = fmaxf(x1, g.x);
        float iy1 = fmaxf(y1, g.y);
        float ix2 = fminf(x2, g.z);
        float iy2 = fminf(y2, g.w);
        float iw  = fmaxf(__fadd_rn(__fsub_rn(ix2, ix1), 1.0f), 0.0f);
        float ih  = fmaxf(__fadd_rn(__fsub_rn(iy2, iy1), 1.0f), 0.0f);
        float inter = __fmul_rn(iw, ih);
        float denom = __fsub_rn(__fadd_rn(areaA, s_ga[k]), inter);
        float ov    = __fmul_rn(__fdiv_rn(inter, denom), s_sc[k]);
        if (ov > best) { best = ov; bestk = k; }   // strict > = argmax first-index
    }

    if (aw == 1.0f && ah == 1.0f) { best = -1.0f; bestk = 0; }  // an_zero row

    g_maxov[b * MM + m] = best;
    g_garg [b * MM + m] = bestk;
}

// ---------------------------------------------------------------------------
// Kernel 2: stable partition (fg first, bg second, original order preserved).
// One 1024-thread block per batch. Ballot/popc warp scans (flags are binary).
// ---------------------------------------------------------------------------
__global__ __launch_bounds__(1024)
void k_scan()
{
    __shared__ int s_wsum[32];
    __shared__ int s_fgtot;
    __shared__ int s_ctot;

    const int b    = blockIdx.x;
    const int t    = threadIdx.x;
    const int lane = t & 31;
    const int wid  = t >> 5;
    const unsigned lt_mask = (1u << lane) - 1u;
    const float* mov = g_maxov + b * MM;

    // Pass 1: total fg count (ballot + popc per chunk)
    int cnt = 0;
    for (int m = t; m < MM; m += 1024) {
        unsigned bal = __ballot_sync(0xffffffffu, mov[m] >= FG_THRESH);
        cnt += __popc(bal);                 // same value across the warp
    }
    if (lane == 0) s_wsum[wid] = cnt;
    __syncthreads();
    if (t == 0) {
        int s = 0;
        for (int w = 0; w < 32; w++) s += s_wsum[w];
        s_fgtot = s;
    }
    __syncthreads();
    const int fgtot = s_fgtot;

    // Pass 2: chunked stable scan -> dest
    int fgrun = 0;
    for (int c0 = 0; c0 < MM; c0 += 1024) {
        int m    = c0 + t;
        int flag = (m < MM) && (mov[m] >= FG_THRESH);

        unsigned bal = __ballot_sync(0xffffffffu, flag);
        int wexcl = __popc(bal & lt_mask);      // exclusive prefix within warp
        int wtot  = __popc(bal);                // warp total
        if (lane == 0) s_wsum[wid] = wtot;
        __syncthreads();
        if (t < 32) {
            int v  = s_wsum[t];
            int xx = v;
            for (int o = 1; o < 32; o <<= 1) {
                int y = __shfl_up_sync(0xffffffffu, xx, o);
                if (t >= o) xx += y;
            }
            if (t == 31) s_ctot = xx;
            s_wsum[t] = xx - v;                 // exclusive warp offsets
        }
        __syncthreads();
        int excl = s_wsum[wid] + wexcl;         // exclusive prefix within chunk
        if (m < MM) {
            int dst = flag ? (fgrun + excl)
                           : (fgtot + (c0 - fgrun) + (t - excl));
            g_dest[b * MM + m] = dst;
        }
        fgrun += s_ctot;
        __syncthreads();
    }
}

// ---------------------------------------------------------------------------
// Kernel 3: scatter all five outputs (vectorized stores where 16B-aligned).
// ---------------------------------------------------------------------------
__global__ __launch_bounds__(256)
void k_write(const float* __restrict__ rois, const float* __restrict__ gt,
             float* __restrict__ out)
{
    const int b = blockIdx.y;
    const int m = blockIdx.x * blockDim.x + threadIdx.x;
    if (m >= MM) return;
    const int idx = b * MM + m;

    float x1, y1, x2, y2;
    if (m < NN) {
        const float* r = rois + ((size_t)b * NN + m) * 5;
        x1 = r[1]; y1 = r[2]; x2 = r[3]; y2 = r[4];
    } else {
        const float* g = gt + ((size_t)b * KK + (m - NN)) * 5;
        x1 = g[0]; y1 = g[1]; x2 = g[2]; y2 = g[3];
    }

    const float best = g_maxov[idx];
    const int   ga   = g_garg[idx];
    const int   d    = g_dest[idx];
    const bool  fg   = (best >= FG_THRESH);

    const float* g = gt + ((size_t)b * KK + ga) * 5;
    const float gx1 = g[0], gy1 = g[1], gx2 = g[2], gy2 = g[3], cls = g[4];

    float*  o_rois = out;
    float*  o_lab  = out   + (size_t)BB * MM * 5;
    float4* o_tgt  = (float4*)(o_lab + (size_t)BB * MM);
    float4* o_in   = o_tgt + (size_t)BB * MM;
    float4* o_out  = o_in  + (size_t)BB * MM;

    const size_t dd = (size_t)b * MM + d;   // permuted position
    const size_t mm = (size_t)b * MM + m;   // original position

    o_rois[dd * 5 + 0] = (float)b;
    o_rois[dd * 5 + 1] = x1;
    o_rois[dd * 5 + 2] = y1;
    o_rois[dd * 5 + 3] = x2;
    o_rois[dd * 5 + 4] = y2;

    o_lab[dd] = fg ? cls : 0.0f;

    float t0 = 0.f, t1 = 0.f, t2 = 0.f, t3 = 0.f;
    if (fg) {
        float ew  = x2 - x1 + 1.0f;
        float eh  = y2 - y1 + 1.0f;
        float ecx = x1 + 0.5f * ew;
        float ecy = y1 + 0.5f * eh;
        float gw  = gx2 - gx1 + 1.0f;
        float gh  = gy2 - gy1 + 1.0f;
        float gcx = gx1 + 0.5f * gw;
        float gcy = gy1 + 0.5f * gh;
        t0 = ((gcx - ecx) / ew) / 0.1f;
        t1 = ((gcy - ecy) / eh) / 0.1f;
        t2 = logf(gw / ew) / 0.2f;
        t3 = logf(gh / eh) / 0.2f;
    }
    o_tgt[dd] = make_float4(t0, t1, t2, t3);

    // focal weights in ORIGINAL roi order
    float om = __fsub_rn(1.0f, best);
    float w  = fg ? __fmul_rn(om, om) : 0.0f;
    float wo = (w > 0.0f) ? 1.0f : 0.0f;   // appended-gt rois: IoU==1 -> w==0 -> 0
    o_in [mm] = make_float4(w,  w,  w,  w);
    o_out[mm] = make_float4(wo, wo, wo, wo);
}

// ---------------------------------------------------------------------------
extern "C" void kernel_launch(void* const* d_in, const int* in_sizes, int n_in,
                              void* d_out, int out_size)
{
    const float* rois = (const float*)d_in[0];   // (B,N,5)
    const float* gt   = (const float*)d_in[1];   // (B,K,5)
    float*       out  = (float*)d_out;

    dim3 grid((MM + 255) / 256, BB);
    k_iou  <<<grid, 256>>>(rois, gt);
    k_scan <<<BB, 1024>>>();
    k_write<<<grid, 256>>>(rois, gt, out);
}

// round 8
// speedup vs baseline: 1.1493x; 1.1493x over previous
#include <cuda_runtime.h>
#include <math.h>

// Problem shape (fixed by the dataset)
#define BB 16
#define NN 8192
#define KK 128
#define MM (NN + KK)          // 8320 = 65 * 128 exactly
#define FG_THRESH 0.5f
#define RPB 128               // rois per block in k_iou
#define KHALF 64              // split-K factor 2

// Scratch (no allocations allowed -> __device__ globals)
__device__ float g_maxov[BB * MM];
__device__ int   g_garg [BB * MM];
__device__ int   g_dest [BB * MM];

// ---------------------------------------------------------------------------
// Kernel 1: per-roi max IoU + argmax over K gt boxes. Split-K x2:
// 256 threads / block, 128 rois / block; threads t<128 scan k in [0,64),
// threads t>=128 scan k in [64,128); combine in smem with first-index
// tiebreak. Zero-area gt boxes get sentinel coords so ov computes to +0
// exactly (matches reference where(gt_zero, 0, ov)) -- no scale multiply.
// Compare-critical arithmetic uses _rn intrinsics (bitwise identical to the
// fp32 reference regardless of contraction / fast-math flags).
// ---------------------------------------------------------------------------
__global__ __launch_bounds__(256)
void k_iou(const float* __restrict__ rois, const float* __restrict__ gt)
{
    __shared__ float4 s_g [KK];    // gt coords (sentinel if zero-area)
    __shared__ float  s_ga[KK];    // gt area
    __shared__ float  s_best[RPB]; // upper-half best
    __shared__ int    s_bk  [RPB]; // upper-half argmax

    const int b    = blockIdx.y;
    const int t    = threadIdx.x;
    const int r    = t & (RPB - 1);   // roi slot within block
    const int half = t >> 7;          // 0: k in [0,64), 1: k in [64,128)

    if (t < KK) {
        const float* g = gt + ((size_t)b * KK + t) * 5;
        float gx1 = g[0], gy1 = g[1], gx2 = g[2], gy2 = g[3];
        float gw = __fadd_rn(__fsub_rn(gx2, gx1), 1.0f);
        float gh = __fadd_rn(__fsub_rn(gy2, gy1), 1.0f);
        bool  z  = (gw == 1.0f && gh == 1.0f);
        s_g[t]  = z ? make_float4(3.0e38f, 3.0e38f, -3.0e38f, -3.0e38f)
                    : make_float4(gx1, gy1, gx2, gy2);
        s_ga[t] = __fmul_rn(gw, gh);
    }
    __syncthreads();

    const int m = blockIdx.x * RPB + r;   // always < MM (65*128 == MM)

    float x1, y1, x2, y2;
    if (m < NN) {
        const float* p = rois + ((size_t)b * NN + m) * 5;
        x1 = p[1]; y1 = p[2]; x2 = p[3]; y2 = p[4];
    } else {
        const float* p = gt + ((size_t)b * KK + (m - NN)) * 5;
        x1 = p[0]; y1 = p[1]; x2 = p[2]; y2 = p[3];
    }

    float aw    = __fadd_rn(__fsub_rn(x2, x1), 1.0f);
    float ah    = __fadd_rn(__fsub_rn(y2, y1), 1.0f);
    float areaA = __fmul_rn(aw, ah);

    float best  = -1e30f;
    int   bestk = 0;
    const int kbase = half * KHALF;

#pragma unroll 8
    for (int kk = 0; kk < KHALF; kk++) {
        const int k = kbase + kk;
        float4 g  = s_g[k];
        float ix1 = fmaxf(x1, g.x);
        float iy1 = fmaxf(y1, g.y);
        float ix2 = fminf(x2, g.z);
        float iy2 = fminf(y2, g.w);
        float iw  = fmaxf(__fadd_rn(__fsub_rn(ix2, ix1), 1.0f), 0.0f);
        float ih  = fmaxf(__fadd_rn(__fsub_rn(iy2, iy1), 1.0f), 0.0f);
        float inter = __fmul_rn(iw, ih);
        float denom = __fsub_rn(__fadd_rn(areaA, s_ga[k]), inter);
        float ov    = __fdiv_rn(inter, denom);
        if (ov > best) { best = ov; bestk = k; }   // strict > = first-index argmax
    }

    if (half == 1) { s_best[r] = best; s_bk[r] = bestk; }
    __syncthreads();

    if (half == 0) {
        float bh = s_best[r];
        if (bh > best) { best = bh; bestk = s_bk[r]; }   // tie -> low half (lower k)
        if (aw == 1.0f && ah == 1.0f) { best = -1.0f; bestk = 0; }  // an_zero row
        g_maxov[b * MM + m] = best;
        g_garg [b * MM + m] = bestk;
    }
}

// ---------------------------------------------------------------------------
// Kernel 2: stable partition (fg first, bg second, original order preserved).
// One 1024-thread block per batch. Ballot/popc warp scans (flags are binary).
// ---------------------------------------------------------------------------
__global__ __launch_bounds__(1024)
void k_scan()
{
    __shared__ int s_wsum[32];
    __shared__ int s_fgtot;
    __shared__ int s_ctot;

    const int b    = blockIdx.x;
    const int t    = threadIdx.x;
    const int lane = t & 31;
    const int wid  = t >> 5;
    const unsigned lt_mask = (1u << lane) - 1u;
    const float* mov = g_maxov + b * MM;

    // Pass 1: total fg count
    int cnt = 0;
    for (int m = t; m < MM; m += 1024) {
        unsigned bal = __ballot_sync(0xffffffffu, mov[m] >= FG_THRESH);
        cnt += __popc(bal);
    }
    if (lane == 0) s_wsum[wid] = cnt;
    __syncthreads();
    if (t == 0) {
        int s = 0;
        for (int w = 0; w < 32; w++) s += s_wsum[w];
        s_fgtot = s;
    }
    __syncthreads();
    const int fgtot = s_fgtot;

    // Pass 2: chunked stable scan -> dest
    int fgrun = 0;
    for (int c0 = 0; c0 < MM; c0 += 1024) {
        int m    = c0 + t;
        int flag = (m < MM) && (mov[m] >= FG_THRESH);

        unsigned bal = __ballot_sync(0xffffffffu, flag);
        int wexcl = __popc(bal & lt_mask);
        int wtot  = __popc(bal);
        if (lane == 0) s_wsum[wid] = wtot;
        __syncthreads();
        if (t < 32) {
            int v  = s_wsum[t];
            int xx = v;
            for (int o = 1; o < 32; o <<= 1) {
                int y = __shfl_up_sync(0xffffffffu, xx, o);
                if (t >= o) xx += y;
            }
            if (t == 31) s_ctot = xx;
            s_wsum[t] = xx - v;
        }
        __syncthreads();
        int excl = s_wsum[wid] + wexcl;
        if (m < MM) {
            int dst = flag ? (fgrun + excl)
                           : (fgtot + (c0 - fgrun) + (t - excl));
            g_dest[b * MM + m] = dst;
        }
        fgrun += s_ctot;
        __syncthreads();
    }
}

// ---------------------------------------------------------------------------
// Kernel 3: scatter all five outputs (vectorized stores where 16B-aligned).
// ---------------------------------------------------------------------------
__global__ __launch_bounds__(256)
void k_write(const float* __restrict__ rois, const float* __restrict__ gt,
             float* __restrict__ out)
{
    const int b = blockIdx.y;
    const int m = blockIdx.x * blockDim.x + threadIdx.x;
    if (m >= MM) return;
    const int idx = b * MM + m;

    float x1, y1, x2, y2;
    if (m < NN) {
        const float* r = rois + ((size_t)b * NN + m) * 5;
        x1 = r[1]; y1 = r[2]; x2 = r[3]; y2 = r[4];
    } else {
        const float* g = gt + ((size_t)b * KK + (m - NN)) * 5;
        x1 = g[0]; y1 = g[1]; x2 = g[2]; y2 = g[3];
    }

    const float best = g_maxov[idx];
    const int   ga   = g_garg[idx];
    const int   d    = g_dest[idx];
    const bool  fg   = (best >= FG_THRESH);

    const float* g = gt + ((size_t)b * KK + ga) * 5;
    const float gx1 = g[0], gy1 = g[1], gx2 = g[2], gy2 = g[3], cls = g[4];

    float*  o_rois = out;
    float*  o_lab  = out   + (size_t)BB * MM * 5;
    float4* o_tgt  = (float4*)(o_lab + (size_t)BB * MM);
    float4* o_in   = o_tgt + (size_t)BB * MM;
    float4* o_out  = o_in  + (size_t)BB * MM;

    const size_t dd = (size_t)b * MM + d;   // permuted position
    const size_t mm = (size_t)b * MM + m;   // original position

    o_rois[dd * 5 + 0] = (float)b;
    o_rois[dd * 5 + 1] = x1;
    o_rois[dd * 5 + 2] = y1;
    o_rois[dd * 5 + 3] = x2;
    o_rois[dd * 5 + 4] = y2;

    o_lab[dd] = fg ? cls : 0.0f;

    float t0 = 0.f, t1 = 0.f, t2 = 0.f, t3 = 0.f;
    if (fg) {
        float ew  = x2 - x1 + 1.0f;
        float eh  = y2 - y1 + 1.0f;
        float ecx = x1 + 0.5f * ew;
        float ecy = y1 + 0.5f * eh;
        float gw  = gx2 - gx1 + 1.0f;
        float gh  = gy2 - gy1 + 1.0f;
        float gcx = gx1 + 0.5f * gw;
        float gcy = gy1 + 0.5f * gh;
        t0 = ((gcx - ecx) / ew) / 0.1f;
        t1 = ((gcy - ecy) / eh) / 0.1f;
        t2 = logf(gw / ew) / 0.2f;
        t3 = logf(gh / eh) / 0.2f;
    }
    o_tgt[dd] = make_float4(t0, t1, t2, t3);

    // focal weights in ORIGINAL roi order
    float om = __fsub_rn(1.0f, best);
    float w  = fg ? __fmul_rn(om, om) : 0.0f;
    float wo = (w > 0.0f) ? 1.0f : 0.0f;   // appended-gt rois: IoU==1 -> w==0 -> 0
    o_in [mm] = make_float4(w,  w,  w,  w);
    o_out[mm] = make_float4(wo, wo, wo, wo);
}

// ---------------------------------------------------------------------------
extern "C" void kernel_launch(void* const* d_in, const int* in_sizes, int n_in,
                              void* d_out, int out_size)
{
    const float* rois = (const float*)d_in[0];   // (B,N,5)
    const float* gt   = (const float*)d_in[1];   // (B,K,5)
    float*       out  = (float*)d_out;

    dim3 grid_iou(MM / RPB, BB);                 // 65 x 16 = 1040 blocks
    k_iou  <<<grid_iou, 256>>>(rois, gt);
    k_scan <<<BB, 1024>>>();
    dim3 grid_w((MM + 255) / 256, BB);
    k_write<<<grid_w, 256>>>(rois, gt, out);
}

// round 9
// speedup vs baseline: 1.3139x; 1.1433x over previous
#include <cuda_runtime.h>
#include <math.h>

// Problem shape (fixed by the dataset)
#define BB 16
#define NN 8192
#define KK 128
#define MM (NN + KK)          // 8320 = 65 * 128 exactly
#define NCHUNK 65             // MM / RPB
#define FG_THRESH 0.5f
#define RPB 128               // rois per block
#define KHALF 64              // split-K factor 2

// Scratch (no allocations allowed -> __device__ globals)
__device__ float g_maxov[BB * MM];
__device__ int   g_garg [BB * MM];
__device__ int   g_blkcnt[BB * NCHUNK];

// Guard band: 1 +- ~2^-19. Clear-greater => rounded quotients strictly
// ordered (gap > 16 ulp). In-band => resolve with the exact reference loop.
#define EPS_HI 1.000002f
#define EPS_LO 0.999998f

// ---------------------------------------------------------------------------
// Kernel 1: per-roi max IoU + argmax, split-K x2, DIVISION-FREE main loop.
// Tracks the exact-ratio argmax via cross-multiplication with a guard band;
// any comparison falling inside the band flags the thread, which then reruns
// the exact reference loop (with __fdiv_rn) -- bitwise-identical semantics.
// max value itself = rn(bi/bd) (monotone rounding commutes with max).
// Epilogue: per-block fg count -> g_blkcnt (replaces the old k_scan).
// ---------------------------------------------------------------------------
__global__ __launch_bounds__(256)
void k_iou(const float* __restrict__ rois, const float* __restrict__ gt)
{
    __shared__ float4 s_g [KK];    // gt coords (sentinel if zero-area)
    __shared__ float  s_ga[KK];    // gt area
    __shared__ float  s_bi[RPB];   // upper-half best inter
    __shared__ float  s_bd[RPB];   // upper-half best denom
    __shared__ int    s_bkf[RPB];  // upper-half argmax | flag<<8
    __shared__ int    s_cnt[8];

    const int b    = blockIdx.y;
    const int t    = threadIdx.x;
    const int r    = t & (RPB - 1);
    const int half = t >> 7;          // 0: k in [0,64), 1: k in [64,128)

    if (t < KK) {
        const float* g = gt + ((size_t)b * KK + t) * 5;
        float gx1 = g[0], gy1 = g[1], gx2 = g[2], gy2 = g[3];
        float gw = __fadd_rn(__fsub_rn(gx2, gx1), 1.0f);
        float gh = __fadd_rn(__fsub_rn(gy2, gy1), 1.0f);
        bool  z  = (gw == 1.0f && gh == 1.0f);
        s_g[t]  = z ? make_float4(3.0e38f, 3.0e38f, -3.0e38f, -3.0e38f)
                    : make_float4(gx1, gy1, gx2, gy2);
        s_ga[t] = __fmul_rn(gw, gh);
    }
    __syncthreads();

    const int m = blockIdx.x * RPB + r;   // always < MM (65*128 == MM)

    float x1, y1, x2, y2;
    if (m < NN) {
        const float* p = rois + ((size_t)b * NN + m) * 5;
        x1 = p[1]; y1 = p[2]; x2 = p[3]; y2 = p[4];
    } else {
        const float* p = gt + ((size_t)b * KK + (m - NN)) * 5;
        x1 = p[0]; y1 = p[1]; x2 = p[2]; y2 = p[3];
    }

    float aw    = __fadd_rn(__fsub_rn(x2, x1), 1.0f);
    float ah    = __fadd_rn(__fsub_rn(y2, y1), 1.0f);
    float areaA = __fmul_rn(aw, ah);

    float bi = 0.0f, bd = 1.0f;    // exact-max tracked as (inter, denom)
    int   bk = 0;
    bool  flag = false;
    const int kbase = half * KHALF;

#pragma unroll 8
    for (int kk = 0; kk < KHALF; kk++) {
        const int k = kbase + kk;
        float4 g  = s_g[k];
        float ix1 = fmaxf(x1, g.x);
        float iy1 = fmaxf(y1, g.y);
        float ix2 = fminf(x2, g.z);
        float iy2 = fminf(y2, g.w);
        float iw  = fmaxf(__fadd_rn(__fsub_rn(ix2, ix1), 1.0f), 0.0f);
        float ih  = fmaxf(__fadd_rn(__fsub_rn(iy2, iy1), 1.0f), 0.0f);
        float inter = __fmul_rn(iw, ih);
        float denom = __fsub_rn(__fadd_rn(areaA, s_ga[k]), inter);
        float lhs = __fmul_rn(inter, bd);
        float rhs = __fmul_rn(bi, denom);
        if (lhs > __fmul_rn(rhs, EPS_HI)) { bi = inter; bd = denom; bk = k; }
        else if (lhs > 0.0f && lhs >= __fmul_rn(rhs, EPS_LO)) flag = true;
    }

    if (half == 1) { s_bi[r] = bi; s_bd[r] = bd; s_bkf[r] = bk | (flag ? 256 : 0); }
    __syncthreads();

    bool fgv = false;
    if (half == 0) {
        // combine with upper half (tie / in-band -> slow path keeps ref order)
        float hbi = s_bi[r], hbd = s_bd[r];
        int   hkf = s_bkf[r];
        flag = flag || (hkf & 256);
        int   hbk = hkf & 255;
        float lhs = __fmul_rn(hbi, bd);
        float rhs = __fmul_rn(bi, hbd);
        if (lhs > __fmul_rn(rhs, EPS_HI)) { bi = hbi; bd = hbd; bk = hbk; }
        else if (lhs > 0.0f && lhs >= __fmul_rn(rhs, EPS_LO)) flag = true;

        float best;
        int   bestk;
        if (flag) {
            // exact reference loop (rare): rounded quotients, strict >, first index
            best = -1e30f; bestk = 0;
#pragma unroll 4
            for (int k = 0; k < KK; k++) {
                float4 g  = s_g[k];
                float ix1 = fmaxf(x1, g.x);
                float iy1 = fmaxf(y1, g.y);
                float ix2 = fminf(x2, g.z);
                float iy2 = fminf(y2, g.w);
                float iw  = fmaxf(__fadd_rn(__fsub_rn(ix2, ix1), 1.0f), 0.0f);
                float ih  = fmaxf(__fadd_rn(__fsub_rn(iy2, iy1), 1.0f), 0.0f);
                float inter = __fmul_rn(iw, ih);
                float denom = __fsub_rn(__fadd_rn(areaA, s_ga[k]), inter);
                float ov    = __fdiv_rn(inter, denom);
                if (ov > best) { best = ov; bestk = k; }
            }
        } else {
            best  = __fdiv_rn(bi, bd);   // rn(max exact) == max of rn's (monotone)
            bestk = bk;
        }

        if (aw == 1.0f && ah == 1.0f) { best = -1.0f; bestk = 0; }  // an_zero row
        g_maxov[b * MM + m] = best;
        g_garg [b * MM + m] = bestk;
        fgv = (best >= FG_THRESH);
    }

    // per-block fg count (warps 0-3 carry real flags; 4-7 contribute 0)
    unsigned bal = __ballot_sync(0xffffffffu, fgv);
    if ((t & 31) == 0) s_cnt[t >> 5] = __popc(bal);
    __syncthreads();
    if (t == 0)
        g_blkcnt[b * NCHUNK + blockIdx.x] = s_cnt[0] + s_cnt[1] + s_cnt[2] + s_cnt[3];
}

// ---------------------------------------------------------------------------
// Kernel 2: compute stable-partition destination inline (chunk prefix from
// g_blkcnt + in-block ballot scan) and scatter all five outputs.
// ---------------------------------------------------------------------------
__global__ __launch_bounds__(128)
void k_write(const float* __restrict__ rois, const float* __restrict__ gt,
             float* __restrict__ out)
{
    __shared__ int s_c[NCHUNK];
    __shared__ int s_w[4];
    __shared__ int s_pre, s_tot;

    const int b   = blockIdx.y;
    const int blk = blockIdx.x;
    const int t   = threadIdx.x;

    if (t < NCHUNK) s_c[t] = g_blkcnt[b * NCHUNK + t];
    __syncthreads();
    if (t == 0) {
        int pre = 0, tot = 0;
        for (int j = 0; j < NCHUNK; j++) {
            int c = s_c[j];
            tot += c;
            if (j < blk) pre += c;
        }
        s_pre = pre; s_tot = tot;
    }

    const int m   = blk * RPB + t;
    const int idx = b * MM + m;

    const float best = g_maxov[idx];
    const int   ga   = g_garg[idx];
    const bool  fg   = (best >= FG_THRESH);

    unsigned bal = __ballot_sync(0xffffffffu, fg);
    if ((t & 31) == 0) s_w[t >> 5] = __popc(bal);
    __syncthreads();

    int lex = __popc(bal & ((1u << (t & 31)) - 1u));
    for (int w = 0; w < (t >> 5); w++) lex += s_w[w];
    const int nfg_before = s_pre + lex;              // fg count before m (batch)
    const int d = fg ? nfg_before : (s_tot + m - nfg_before);

    float x1, y1, x2, y2;
    if (m < NN) {
        const float* r = rois + ((size_t)b * NN + m) * 5;
        x1 = r[1]; y1 = r[2]; x2 = r[3]; y2 = r[4];
    } else {
        const float* g = gt + ((size_t)b * KK + (m - NN)) * 5;
        x1 = g[0]; y1 = g[1]; x2 = g[2]; y2 = g[3];
    }

    const float* g = gt + ((size_t)b * KK + ga) * 5;
    const float gx1 = g[0], gy1 = g[1], gx2 = g[2], gy2 = g[3], cls = g[4];

    float*  o_rois = out;
    float*  o_lab  = out   + (size_t)BB * MM * 5;
    float4* o_tgt  = (float4*)(o_lab + (size_t)BB * MM);
    float4* o_in   = o_tgt + (size_t)BB * MM;
    float4* o_out  = o_in  + (size_t)BB * MM;

    const size_t dd = (size_t)b * MM + d;   // permuted position
    const size_t mm = (size_t)idx;          // original position

    o_rois[dd * 5 + 0] = (float)b;
    o_rois[dd * 5 + 1] = x1;
    o_rois[dd * 5 + 2] = y1;
    o_rois[dd * 5 + 3] = x2;
    o_rois[dd * 5 + 4] = y2;

    o_lab[dd] = fg ? cls : 0.0f;

    float t0 = 0.f, t1 = 0.f, t2 = 0.f, t3 = 0.f;
    if (fg) {
        float ew  = x2 - x1 + 1.0f;
        float eh  = y2 - y1 + 1.0f;
        float ecx = x1 + 0.5f * ew;
        float ecy = y1 + 0.5f * eh;
        float gw  = gx2 - gx1 + 1.0f;
        float gh  = gy2 - gy1 + 1.0f;
        float gcx = gx1 + 0.5f * gw;
        float gcy = gy1 + 0.5f * gh;
        t0 = ((gcx - ecx) / ew) / 0.1f;
        t1 = ((gcy - ecy) / eh) / 0.1f;
        t2 = logf(gw / ew) / 0.2f;
        t3 = logf(gh / eh) / 0.2f;
    }
    o_tgt[dd] = make_float4(t0, t1, t2, t3);

    // focal weights in ORIGINAL roi order
    float om = __fsub_rn(1.0f, best);
    float w  = fg ? __fmul_rn(om, om) : 0.0f;
    float wo = (w > 0.0f) ? 1.0f : 0.0f;   // appended-gt rois: IoU==1 -> w==0 -> 0
    o_in [mm] = make_float4(w,  w,  w,  w);
    o_out[mm] = make_float4(wo, wo, wo, wo);
}

// ---------------------------------------------------------------------------
extern "C" void kernel_launch(void* const* d_in, const int* in_sizes, int n_in,
                              void* d_out, int out_size)
{
    const float* rois = (const float*)d_in[0];   // (B,N,5)
    const float* gt   = (const float*)d_in[1];   // (B,K,5)
    float*       out  = (float*)d_out;

    dim3 grid(NCHUNK, BB);                       // 65 x 16 = 1040 blocks
    k_iou  <<<grid, 256>>>(rois, gt);
    k_write<<<grid, 128>>>(rois, gt, out);
}